// round 13
// baseline (speedup 1.0000x reference)
#include <cuda_runtime.h>
#include <cuda_fp16.h>
#include <cstdint>

#define N_ 2
#define LQ_ 4000
#define C_ 256
#define M_ 8
#define L_ 4
#define P_ 4
#define D_ 32
#define LIN_ 5440   // 64*64 + 32*32 + 16*16 + 8*8

// Scratch (static device globals; no allocation allowed)
__device__ __half g_kv [N_ * LIN_ * M_ * 64];  // [N,Lin,M,{k[32]|v[32]}]
__device__ float  g_q  [N_ * LQ_ * C_];
__device__ float  g_off[N_ * LQ_ * C_];
__device__ __half g_att[N_ * LQ_ * C_];
__device__ __half g_qh [N_ * LQ_ * C_];
__device__ __half g_inh[N_ * LIN_ * C_];
__device__ __half g_wh [5 * C_ * C_];          // Wk, Wv, Wq, Woff, Wout

// ---------------------------------------------------------------------------
// Single fused fp32 -> fp16 converter (7 tensors, grid.y selects)
// ---------------------------------------------------------------------------
struct CvtAll { const float* src[7]; __half* dst[7]; int n[7]; };
__global__ void f2h_all_kernel(CvtAll c) {
    const int which = blockIdx.y;
    const int i = (blockIdx.x * blockDim.x + threadIdx.x) * 4;
    if (i < c.n[which]) {
        float4 v = *reinterpret_cast<const float4*>(c.src[which] + i);
        __half2* p = reinterpret_cast<__half2*>(c.dst[which] + i);
        p[0] = __floats2half2_rn(v.x, v.y);
        p[1] = __floats2half2_rn(v.z, v.w);
    }
}

__device__ __forceinline__ uint32_t smem_u32(const void* p) {
    return static_cast<uint32_t>(__cvta_generic_to_shared(p));
}
__device__ __forceinline__ void cp16(uint32_t dst, const void* src) {
    asm volatile("cp.async.cg.shared.global [%0], [%1], 16;" :: "r"(dst), "l"(src));
}
__device__ __forceinline__ void cp_commit() {
    asm volatile("cp.async.commit_group;");
}
template<int NN>
__device__ __forceinline__ void cp_wait() {
    asm volatile("cp.async.wait_group %0;" :: "n"(NN));
}

// ---------------------------------------------------------------------------
// HMMA GEMM, fp16 inputs, 3-stage cp.async ring (ONE syncthreads per K-iter).
// Columns 0..255 use W, bias b0 -> out slot 0; 256..511 use W+65536, b1 -> 1.
// MODE 0: dual fp32 outs.  MODE 1: kv interleave (half).  MODE 2: single fp32.
// ---------------------------------------------------------------------------
template<int MODE>
__global__ __launch_bounds__(256) void gemm_mma(
    const __half* __restrict__ A, const __half* __restrict__ W,
    const float* __restrict__ b0, const float* __restrict__ b1,
    void* __restrict__ out0, void* __restrict__ out1, int rows)
{
    __shared__ __half As[3][128 * 40];
    __shared__ __half Bs[3][32 * 64];

    const int tid = threadIdx.x;
    const int lane = tid & 31;
    const int wm = (tid >> 5) & 3;
    const int wn = tid >> 7;
    const int row0 = blockIdx.y * 128;
    const int col0 = blockIdx.x * 64;
    const int wsel = col0 >> 8;
    const int colw = col0 & 255;

    const int ar = tid >> 2;
    const int ac = tid & 3;
    const __half* Ag0 = A + (size_t)min(row0 + ar,      rows - 1) * 256 + ac * 8;
    const __half* Ag1 = A + (size_t)min(row0 + ar + 64, rows - 1) * 256 + ac * 8;
    const uint32_t sA0 = smem_u32(&As[0][ar * 40 + ac * 8]);
    const uint32_t sA1 = smem_u32(&As[0][(ar + 64) * 40 + ac * 8]);
    const int bk = tid >> 3;
    const int bc = tid & 7;
    const __half* Bg = W + wsel * 65536 + (size_t)bk * 256 + colw + bc * 8;
    const uint32_t sB = smem_u32(&Bs[0][bk * 64 + ((bc ^ (bk & 7)) * 8)]);

    const uint32_t stA = 128 * 40 * 2;
    const uint32_t stB = 32 * 64 * 2;

    cp16(sA0, Ag0);
    cp16(sA1, Ag1);
    cp16(sB,  Bg);
    cp_commit();
    cp16(sA0 + stA, Ag0 + 32);
    cp16(sA1 + stA, Ag1 + 32);
    cp16(sB  + stB, Bg + (size_t)32 * 256);
    cp_commit();

    float acc[2][4][4];
#pragma unroll
    for (int mt = 0; mt < 2; mt++)
#pragma unroll
        for (int nt = 0; nt < 4; nt++)
#pragma unroll
            for (int i = 0; i < 4; i++) acc[mt][nt][i] = 0.0f;

    const int ltile = lane >> 3;
    const int ltr   = lane & 7;
    const int a_row_base = wm * 32 + (ltile & 1) * 8 + ltr;
    const int a_ch_off   = ltile >> 1;
    const int b_k_base   = (ltile & 1) * 8 + ltr;
    const int b_ch_off   = ltile >> 1;

#pragma unroll
    for (int it = 0; it < 8; it++) {
        cp_wait<1>();
        __syncthreads();

        const int ps = (it + 2) % 3;
        if (it < 6) {
            const int koff = (it + 2) * 32;
            cp16(sA0 + ps * stA, Ag0 + koff);
            cp16(sA1 + ps * stA, Ag1 + koff);
            cp16(sB  + ps * stB, Bg + (size_t)koff * 256);
        }
        cp_commit();

        const int buf = it % 3;
        const __half* Ab = As[buf];
        const __half* Bb = Bs[buf];
#pragma unroll
        for (int ks = 0; ks < 2; ks++) {
            uint32_t a[2][4], b[2][4];
#pragma unroll
            for (int mt = 0; mt < 2; mt++) {
                const int row = a_row_base + mt * 16;
                const int ch  = ks * 2 + a_ch_off;
                uint32_t addr = smem_u32(&Ab[row * 40 + ch * 8]);
                asm volatile(
                    "ldmatrix.sync.aligned.m8n8.x4.shared.b16 {%0,%1,%2,%3}, [%4];"
                    : "=r"(a[mt][0]), "=r"(a[mt][1]), "=r"(a[mt][2]), "=r"(a[mt][3])
                    : "r"(addr));
            }
#pragma unroll
            for (int p = 0; p < 2; p++) {
                const int k = ks * 16 + b_k_base;
                const int c = wn * 4 + p * 2 + b_ch_off;
                uint32_t addr = smem_u32(&Bb[k * 64 + ((c ^ (k & 7)) * 8)]);
                asm volatile(
                    "ldmatrix.sync.aligned.m8n8.x4.trans.shared.b16 {%0,%1,%2,%3}, [%4];"
                    : "=r"(b[p][0]), "=r"(b[p][1]), "=r"(b[p][2]), "=r"(b[p][3])
                    : "r"(addr));
            }
#pragma unroll
            for (int mt = 0; mt < 2; mt++)
#pragma unroll
                for (int nt = 0; nt < 4; nt++) {
                    const uint32_t bb0 = b[nt >> 1][(nt & 1) * 2 + 0];
                    const uint32_t bb1 = b[nt >> 1][(nt & 1) * 2 + 1];
                    asm volatile(
                        "mma.sync.aligned.m16n8k16.row.col.f32.f16.f16.f32 "
                        "{%0,%1,%2,%3}, {%4,%5,%6,%7}, {%8,%9}, {%0,%1,%2,%3};"
                        : "+f"(acc[mt][nt][0]), "+f"(acc[mt][nt][1]),
                          "+f"(acc[mt][nt][2]), "+f"(acc[mt][nt][3])
                        : "r"(a[mt][0]), "r"(a[mt][1]), "r"(a[mt][2]), "r"(a[mt][3]),
                          "r"(bb0), "r"(bb1));
                }
        }
    }

    const int g  = lane >> 2;
    const int qd = lane & 3;
    const float* bp = wsel ? b1 : b0;
#pragma unroll
    for (int mt = 0; mt < 2; mt++) {
        const int rlo = row0 + wm * 32 + mt * 16 + g;
        const int rhi = rlo + 8;
#pragma unroll
        for (int nt = 0; nt < 4; nt++) {
            const int n = col0 + wn * 32 + nt * 8 + qd * 2;
            const int c = n & 255;
            const float2 bb = *reinterpret_cast<const float2*>(&bp[c]);
            float v0 = acc[mt][nt][0] + bb.x, v1 = acc[mt][nt][1] + bb.y;
            float v2 = acc[mt][nt][2] + bb.x, v3 = acc[mt][nt][3] + bb.y;
            if (MODE == 1) {
                const int oc = ((c >> 5) << 6) + (c & 31) + (wsel ? 32 : 0);
                __half* o = (__half*)out0;
                if (rlo < rows)
                    *reinterpret_cast<__half2*>(&o[(size_t)rlo * 512 + oc]) = __floats2half2_rn(v0, v1);
                if (rhi < rows)
                    *reinterpret_cast<__half2*>(&o[(size_t)rhi * 512 + oc]) = __floats2half2_rn(v2, v3);
            } else {
                float* o = (MODE == 2) ? (float*)out0 : (wsel ? (float*)out1 : (float*)out0);
                if (rlo < rows)
                    *reinterpret_cast<float2*>(&o[(size_t)rlo * 256 + c]) = make_float2(v0, v1);
                if (rhi < rows)
                    *reinterpret_cast<float2*>(&o[(size_t)rhi * 256 + c]) = make_float2(v2, v3);
            }
        }
    }
}

// ---------------------------------------------------------------------------
// Sampling + key-aware attention. One warp per (n, q, m).
// R11 pairwise structure + packed half2 reduction, with ONLINE no-max
// softmax: exp-weight and accumulate each pair immediately, so no
// logits[16]/sv0[16]/sv1[16] arrays stay live (regs 64 -> ~45).
// ---------------------------------------------------------------------------
__global__ __launch_bounds__(256) void sample_attn_kernel(
    const float* __restrict__ ref)   // [N, Lq, L, 2]
{
    const int w = blockIdx.x * 8 + (threadIdx.x >> 5);
    const int lane = threadIdx.x & 31;
    if (w >= N_ * LQ_ * M_) return;

    const int m  = w & 7;
    const int nq = w >> 3;
    const int n  = nq / LQ_;

    const int is_v = lane >> 4;
    const int cl = (lane & 15) * 2;

    float2 qd = make_float2(0.0f, 0.0f);
    if (!is_v) qd = *reinterpret_cast<const float2*>(&g_q[(nq * M_ + m) * D_ + cl]);

    const float* offp = g_off + nq * 256 + m * 32;
    const float* refp = ref + nq * 8;

    const int HWs[4]    = {64, 32, 16, 8};
    const int starts[4] = {0, 4096, 5120, 5376};
    const float SCALE = 0.17677669529663687f;   // 1/sqrt(32)

    float ssum = 0.0f, o0 = 0.0f, o1 = 0.0f;

#pragma unroll
    for (int l = 0; l < L_; l++) {
        const float rx = refp[l * 2 + 0];
        const float ry = refp[l * 2 + 1];
        const int HW = HWs[l];
        const float fHW = (float)HW;
        const float fx = rx * fHW - 0.5f;
        const float fy = ry * fHW - 0.5f;
        const int base = (n * LIN_ + starts[l]) * M_ + m;

#pragma unroll
        for (int pp = 0; pp < 2; pp++) {      // pairs of points
            const int pa = l * 4 + pp * 2;

            // both points' offsets in one 16B load (pa even -> aligned)
            const float4 o4 = *reinterpret_cast<const float4*>(&offp[pa * 2]);
            const float xA = fx + o4.x, yA = fy + o4.y;
            const float xB = fx + o4.z, yB = fy + o4.w;
            const float xA0f = floorf(xA), yA0f = floorf(yA);
            const float xB0f = floorf(xB), yB0f = floorf(yB);
            const float txA = xA - xA0f, tyA = yA - yA0f;
            const float txB = xB - xB0f, tyB = yB - yB0f;
            const int xA0 = (int)xA0f, yA0 = (int)yA0f;
            const int xB0 = (int)xB0f, yB0 = (int)yB0f;

            float a0 = 0.0f, a1 = 0.0f, b0 = 0.0f, b1 = 0.0f;
#pragma unroll
            for (int c = 0; c < 4; c++) {
                const int dx = c & 1;
                const int dy = c >> 1;
                // point A corner
                {
                    const int xi = xA0 + dx, yi = yA0 + dy;
                    if (xi >= 0 && xi < HW && yi >= 0 && yi < HW) {
                        const float wgt = (dx ? txA : 1.0f - txA) * (dy ? tyA : 1.0f - tyA);
                        const int idx = (base + (yi * HW + xi) * M_) * 64 + lane * 2;
                        const float2 f = __half22float2(
                            *reinterpret_cast<const __half2*>(&g_kv[idx]));
                        a0 = fmaf(wgt, f.x, a0);
                        a1 = fmaf(wgt, f.y, a1);
                    }
                }
                // point B corner
                {
                    const int xi = xB0 + dx, yi = yB0 + dy;
                    if (xi >= 0 && xi < HW && yi >= 0 && yi < HW) {
                        const float wgt = (dx ? txB : 1.0f - txB) * (dy ? tyB : 1.0f - tyB);
                        const int idx = (base + (yi * HW + xi) * M_) * 64 + lane * 2;
                        const float2 f = __half22float2(
                            *reinterpret_cast<const __half2*>(&g_kv[idx]));
                        b0 = fmaf(wgt, f.x, b0);
                        b1 = fmaf(wgt, f.y, b1);
                    }
                }
            }

            // scaled key partials; packed reduction for both points at once
            float lgA = is_v ? 0.0f : fmaf(qd.x, a0, qd.y * a1) * SCALE;
            float lgB = is_v ? 0.0f : fmaf(qd.x, b0, qd.y * b1) * SCALE;
            __half2 hl = __floats2half2_rn(lgA, lgB);
#pragma unroll
            for (int s = 16; s > 0; s >>= 1) {
                uint32_t u = *reinterpret_cast<uint32_t*>(&hl);
                uint32_t v = __shfl_xor_sync(0xffffffffu, u, s);
                hl = __hadd2(hl, *reinterpret_cast<__half2*>(&v));
            }
            const float2 lf = __half22float2(hl);

            // online no-max softmax accumulation (logits are O(0.1))
            const float eA = __expf(lf.x);
            const float eB = __expf(lf.y);
            ssum += eA + eB;
            o0 = fmaf(eA, a0, o0); o1 = fmaf(eA, a1, o1);
            o0 = fmaf(eB, b0, o0); o1 = fmaf(eB, b1, o1);
        }
    }

    if (is_v) {
        const float inv = 1.0f / ssum;
        *reinterpret_cast<__half2*>(&g_att[(nq * M_ + m) * D_ + cl]) =
            __floats2half2_rn(o0 * inv, o1 * inv);
    }
}

// ---------------------------------------------------------------------------
extern "C" void kernel_launch(void* const* d_in, const int* in_sizes, int n_in,
                              void* d_out, int out_size)
{
    const float* query = (const float*)d_in[0];
    const float* ref   = (const float*)d_in[1];
    const float* inp   = (const float*)d_in[2];
    const float* Wv   = (const float*)d_in[5];
    const float* bv   = (const float*)d_in[6];
    const float* Wk   = (const float*)d_in[7];
    const float* bk   = (const float*)d_in[8];
    const float* Wq   = (const float*)d_in[9];
    const float* bq   = (const float*)d_in[10];
    const float* Woff = (const float*)d_in[11];
    const float* boff = (const float*)d_in[12];
    const float* Wout = (const float*)d_in[13];
    const float* bout = (const float*)d_in[14];
    float* out = (float*)d_out;

    void *pkv, *pq, *po, *pa, *pqh, *pinh, *pwh;
    cudaGetSymbolAddress(&pkv,  g_kv);
    cudaGetSymbolAddress(&pq,   g_q);
    cudaGetSymbolAddress(&po,   g_off);
    cudaGetSymbolAddress(&pa,   g_att);
    cudaGetSymbolAddress(&pqh,  g_qh);
    cudaGetSymbolAddress(&pinh, g_inh);
    cudaGetSymbolAddress(&pwh,  g_wh);

    const int rowsV = N_ * LIN_;   // 10880
    const int rowsQ = N_ * LQ_;    // 8000
    const int gyV = rowsV / 128;          // 85
    const int gyQ = (rowsQ + 127) / 128;  // 63

    const int nQ = rowsQ * 256;
    const int nV = rowsV * 256;

    __half* wh = (__half*)pwh;
    CvtAll ca;
    ca.src[0] = inp;   ca.dst[0] = (__half*)pinh; ca.n[0] = nV;
    ca.src[1] = query; ca.dst[1] = (__half*)pqh;  ca.n[1] = nQ;
    const float* wsrc[5] = {Wk, Wv, Wq, Woff, Wout};
    for (int i = 0; i < 5; i++) {
        ca.src[2 + i] = wsrc[i];
        ca.dst[2 + i] = wh + i * 65536;
        ca.n[2 + i] = 65536;
    }
    f2h_all_kernel<<<dim3((nV / 4 + 255) / 256, 7), 256>>>(ca);

    gemm_mma<1><<<dim3(8, gyV), 256>>>((const __half*)pinh, wh + 0 * 65536,
                                       bk, bv, pkv, nullptr, rowsV);
    gemm_mma<0><<<dim3(8, gyQ), 256>>>((const __half*)pqh, wh + 2 * 65536,
                                       bq, boff, pq, po, rowsQ);

    const int nwarps = N_ * LQ_ * M_;          // 64000
    sample_attn_kernel<<<(nwarps + 7) / 8, 256>>>(ref);

    gemm_mma<2><<<dim3(4, gyQ), 256>>>((const __half*)pa, wh + 4 * 65536,
                                       bout, bout, out, nullptr, rowsQ);
}

// round 14
// speedup vs baseline: 1.2958x; 1.2958x over previous
#include <cuda_runtime.h>
#include <cuda_fp16.h>
#include <cstdint>

#define N_ 2
#define LQ_ 4000
#define C_ 256
#define M_ 8
#define L_ 4
#define P_ 4
#define D_ 32
#define LIN_ 5440   // 64*64 + 32*32 + 16*16 + 8*8

// Scratch (static device globals; no allocation allowed)
// g_kv cell layout (64 halves per (pos, m)): group g in 0..15 holds
// {k[2g], k[2g+1], v[2g], v[2g+1]} at halves [4g..4g+3].
__device__ __half g_kv [N_ * LIN_ * M_ * 64];
__device__ float  g_q  [N_ * LQ_ * C_];
__device__ float  g_off[N_ * LQ_ * C_];
__device__ __half g_att[N_ * LQ_ * C_];
__device__ __half g_qh [N_ * LQ_ * C_];
__device__ __half g_inh[N_ * LIN_ * C_];
__device__ __half g_wh [5 * C_ * C_];          // Wk, Wv, Wq, Woff, Wout

// ---------------------------------------------------------------------------
// Single fused fp32 -> fp16 converter (7 tensors, grid.y selects)
// ---------------------------------------------------------------------------
struct CvtAll { const float* src[7]; __half* dst[7]; int n[7]; };
__global__ void f2h_all_kernel(CvtAll c) {
    const int which = blockIdx.y;
    const int i = (blockIdx.x * blockDim.x + threadIdx.x) * 4;
    if (i < c.n[which]) {
        float4 v = *reinterpret_cast<const float4*>(c.src[which] + i);
        __half2* p = reinterpret_cast<__half2*>(c.dst[which] + i);
        p[0] = __floats2half2_rn(v.x, v.y);
        p[1] = __floats2half2_rn(v.z, v.w);
    }
}

__device__ __forceinline__ uint32_t smem_u32(const void* p) {
    return static_cast<uint32_t>(__cvta_generic_to_shared(p));
}
__device__ __forceinline__ void cp16(uint32_t dst, const void* src) {
    asm volatile("cp.async.cg.shared.global [%0], [%1], 16;" :: "r"(dst), "l"(src));
}
__device__ __forceinline__ void cp_commit() {
    asm volatile("cp.async.commit_group;");
}
template<int NN>
__device__ __forceinline__ void cp_wait() {
    asm volatile("cp.async.wait_group %0;" :: "n"(NN));
}

// ---------------------------------------------------------------------------
// HMMA GEMM, fp16 inputs, 3-stage cp.async ring (ONE syncthreads per K-iter).
// Columns 0..255 use W, bias b0 -> out slot 0; 256..511 use W+65536, b1 -> 1.
// MODE 0: dual fp32 outs.  MODE 1: kv group-interleave (half).  MODE 2: fp32.
// ---------------------------------------------------------------------------
template<int MODE>
__global__ __launch_bounds__(256) void gemm_mma(
    const __half* __restrict__ A, const __half* __restrict__ W,
    const float* __restrict__ b0, const float* __restrict__ b1,
    void* __restrict__ out0, void* __restrict__ out1, int rows)
{
    __shared__ __half As[3][128 * 40];
    __shared__ __half Bs[3][32 * 64];

    const int tid = threadIdx.x;
    const int lane = tid & 31;
    const int wm = (tid >> 5) & 3;
    const int wn = tid >> 7;
    const int row0 = blockIdx.y * 128;
    const int col0 = blockIdx.x * 64;
    const int wsel = col0 >> 8;
    const int colw = col0 & 255;

    const int ar = tid >> 2;
    const int ac = tid & 3;
    const __half* Ag0 = A + (size_t)min(row0 + ar,      rows - 1) * 256 + ac * 8;
    const __half* Ag1 = A + (size_t)min(row0 + ar + 64, rows - 1) * 256 + ac * 8;
    const uint32_t sA0 = smem_u32(&As[0][ar * 40 + ac * 8]);
    const uint32_t sA1 = smem_u32(&As[0][(ar + 64) * 40 + ac * 8]);
    const int bk = tid >> 3;
    const int bc = tid & 7;
    const __half* Bg = W + wsel * 65536 + (size_t)bk * 256 + colw + bc * 8;
    const uint32_t sB = smem_u32(&Bs[0][bk * 64 + ((bc ^ (bk & 7)) * 8)]);

    const uint32_t stA = 128 * 40 * 2;
    const uint32_t stB = 32 * 64 * 2;

    cp16(sA0, Ag0);
    cp16(sA1, Ag1);
    cp16(sB,  Bg);
    cp_commit();
    cp16(sA0 + stA, Ag0 + 32);
    cp16(sA1 + stA, Ag1 + 32);
    cp16(sB  + stB, Bg + (size_t)32 * 256);
    cp_commit();

    float acc[2][4][4];
#pragma unroll
    for (int mt = 0; mt < 2; mt++)
#pragma unroll
        for (int nt = 0; nt < 4; nt++)
#pragma unroll
            for (int i = 0; i < 4; i++) acc[mt][nt][i] = 0.0f;

    const int ltile = lane >> 3;
    const int ltr   = lane & 7;
    const int a_row_base = wm * 32 + (ltile & 1) * 8 + ltr;
    const int a_ch_off   = ltile >> 1;
    const int b_k_base   = (ltile & 1) * 8 + ltr;
    const int b_ch_off   = ltile >> 1;

#pragma unroll
    for (int it = 0; it < 8; it++) {
        cp_wait<1>();
        __syncthreads();

        const int ps = (it + 2) % 3;
        if (it < 6) {
            const int koff = (it + 2) * 32;
            cp16(sA0 + ps * stA, Ag0 + koff);
            cp16(sA1 + ps * stA, Ag1 + koff);
            cp16(sB  + ps * stB, Bg + (size_t)koff * 256);
        }
        cp_commit();

        const int buf = it % 3;
        const __half* Ab = As[buf];
        const __half* Bb = Bs[buf];
#pragma unroll
        for (int ks = 0; ks < 2; ks++) {
            uint32_t a[2][4], b[2][4];
#pragma unroll
            for (int mt = 0; mt < 2; mt++) {
                const int row = a_row_base + mt * 16;
                const int ch  = ks * 2 + a_ch_off;
                uint32_t addr = smem_u32(&Ab[row * 40 + ch * 8]);
                asm volatile(
                    "ldmatrix.sync.aligned.m8n8.x4.shared.b16 {%0,%1,%2,%3}, [%4];"
                    : "=r"(a[mt][0]), "=r"(a[mt][1]), "=r"(a[mt][2]), "=r"(a[mt][3])
                    : "r"(addr));
            }
#pragma unroll
            for (int p = 0; p < 2; p++) {
                const int k = ks * 16 + b_k_base;
                const int c = wn * 4 + p * 2 + b_ch_off;
                uint32_t addr = smem_u32(&Bb[k * 64 + ((c ^ (k & 7)) * 8)]);
                asm volatile(
                    "ldmatrix.sync.aligned.m8n8.x4.trans.shared.b16 {%0,%1,%2,%3}, [%4];"
                    : "=r"(b[p][0]), "=r"(b[p][1]), "=r"(b[p][2]), "=r"(b[p][3])
                    : "r"(addr));
            }
#pragma unroll
            for (int mt = 0; mt < 2; mt++)
#pragma unroll
                for (int nt = 0; nt < 4; nt++) {
                    const uint32_t bb0 = b[nt >> 1][(nt & 1) * 2 + 0];
                    const uint32_t bb1 = b[nt >> 1][(nt & 1) * 2 + 1];
                    asm volatile(
                        "mma.sync.aligned.m16n8k16.row.col.f32.f16.f16.f32 "
                        "{%0,%1,%2,%3}, {%4,%5,%6,%7}, {%8,%9}, {%0,%1,%2,%3};"
                        : "+f"(acc[mt][nt][0]), "+f"(acc[mt][nt][1]),
                          "+f"(acc[mt][nt][2]), "+f"(acc[mt][nt][3])
                        : "r"(a[mt][0]), "r"(a[mt][1]), "r"(a[mt][2]), "r"(a[mt][3]),
                          "r"(bb0), "r"(bb1));
                }
        }
    }

    const int g  = lane >> 2;
    const int qd = lane & 3;
    const float* bp = wsel ? b1 : b0;
#pragma unroll
    for (int mt = 0; mt < 2; mt++) {
        const int rlo = row0 + wm * 32 + mt * 16 + g;
        const int rhi = rlo + 8;
#pragma unroll
        for (int nt = 0; nt < 4; nt++) {
            const int n = col0 + wn * 32 + nt * 8 + qd * 2;
            const int c = n & 255;
            const float2 bb = *reinterpret_cast<const float2*>(&bp[c]);
            float v0 = acc[mt][nt][0] + bb.x, v1 = acc[mt][nt][1] + bb.y;
            float v2 = acc[mt][nt][2] + bb.x, v3 = acc[mt][nt][3] + bb.y;
            if (MODE == 1) {
                // kv group-interleave: d = c&31 (even); k pair at m*64 + 2d,
                // v pair at m*64 + 2d + 2  (still an adjacent half2 write)
                const int oc = ((c >> 5) << 6) + 2 * (c & 31) + (wsel ? 2 : 0);
                __half* o = (__half*)out0;
                if (rlo < rows)
                    *reinterpret_cast<__half2*>(&o[(size_t)rlo * 512 + oc]) = __floats2half2_rn(v0, v1);
                if (rhi < rows)
                    *reinterpret_cast<__half2*>(&o[(size_t)rhi * 512 + oc]) = __floats2half2_rn(v2, v3);
            } else {
                float* o = (MODE == 2) ? (float*)out0 : (wsel ? (float*)out1 : (float*)out0);
                if (rlo < rows)
                    *reinterpret_cast<float2*>(&o[(size_t)rlo * 256 + c]) = make_float2(v0, v1);
                if (rhi < rows)
                    *reinterpret_cast<float2*>(&o[(size_t)rhi * 256 + c]) = make_float2(v2, v3);
            }
        }
    }
}

// ---------------------------------------------------------------------------
// Sampling + key-aware attention. ONE WARP = TWO (n,q,m) items: half-warp
// per item, each sub-lane (sl=lane&15) owns channel pair {2sl,2sl+1} of BOTH
// k and v via one 8B load per corner. Pairwise point pipeline + packed
// half2 logit reduction (span-16 tree reduces both items simultaneously) +
// online no-max softmax.
// ---------------------------------------------------------------------------
__global__ __launch_bounds__(256) void sample_attn_kernel(
    const float* __restrict__ ref)   // [N, Lq, L, 2]
{
    const int warp = blockIdx.x * 8 + (threadIdx.x >> 5);
    const int lane = threadIdx.x & 31;
    const int item = warp * 2 + (lane >> 4);     // nq*M + m
    if (item >= N_ * LQ_ * M_) return;

    const int m  = item & 7;
    const int nq = item >> 3;
    const int n  = nq / LQ_;
    const int sl = lane & 15;
    const int cl = sl * 2;

    const float2 qd = *reinterpret_cast<const float2*>(&g_q[item * 32 + cl]);

    const float* offp = g_off + nq * 256 + m * 32;
    const float* refp = ref + nq * 8;

    const int HWs[4]    = {64, 32, 16, 8};
    const int starts[4] = {0, 4096, 5120, 5376};
    const float SCALE = 0.17677669529663687f;   // 1/sqrt(32)

    float ssum = 0.0f, o0 = 0.0f, o1 = 0.0f;

#pragma unroll
    for (int l = 0; l < L_; l++) {
        const float rx = refp[l * 2 + 0];
        const float ry = refp[l * 2 + 1];
        const int HW = HWs[l];
        const float fHW = (float)HW;
        const float fx = rx * fHW - 0.5f;
        const float fy = ry * fHW - 0.5f;
        const int base = (n * LIN_ + starts[l]) * M_ + m;

#pragma unroll
        for (int pp = 0; pp < 2; pp++) {      // pairs of points
            const int pa = l * 4 + pp * 2;

            // both points' offsets in one 16B load (pa even -> aligned)
            const float4 o4 = *reinterpret_cast<const float4*>(&offp[pa * 2]);
            const float xA = fx + o4.x, yA = fy + o4.y;
            const float xB = fx + o4.z, yB = fy + o4.w;
            const float xA0f = floorf(xA), yA0f = floorf(yA);
            const float xB0f = floorf(xB), yB0f = floorf(yB);
            const float txA = xA - xA0f, tyA = yA - yA0f;
            const float txB = xB - xB0f, tyB = yB - yB0f;
            const int xA0 = (int)xA0f, yA0 = (int)yA0f;
            const int xB0 = (int)xB0f, yB0 = (int)yB0f;

            // per-lane accumulators: k pair + v pair, points A and B
            float ak0 = 0.0f, ak1 = 0.0f, av0 = 0.0f, av1 = 0.0f;
            float bk0 = 0.0f, bk1 = 0.0f, bv0 = 0.0f, bv1 = 0.0f;
#pragma unroll
            for (int c = 0; c < 4; c++) {
                const int dx = c & 1;
                const int dy = c >> 1;
                // point A corner
                {
                    const int xi = xA0 + dx, yi = yA0 + dy;
                    if (xi >= 0 && xi < HW && yi >= 0 && yi < HW) {
                        const float wgt = (dx ? txA : 1.0f - txA) * (dy ? tyA : 1.0f - tyA);
                        const int idx = (base + (yi * HW + xi) * M_) * 64 + sl * 4;
                        const uint2 u = *reinterpret_cast<const uint2*>(&g_kv[idx]);
                        const float2 kk = __half22float2(*reinterpret_cast<const __half2*>(&u.x));
                        const float2 vv = __half22float2(*reinterpret_cast<const __half2*>(&u.y));
                        ak0 = fmaf(wgt, kk.x, ak0); ak1 = fmaf(wgt, kk.y, ak1);
                        av0 = fmaf(wgt, vv.x, av0); av1 = fmaf(wgt, vv.y, av1);
                    }
                }
                // point B corner
                {
                    const int xi = xB0 + dx, yi = yB0 + dy;
                    if (xi >= 0 && xi < HW && yi >= 0 && yi < HW) {
                        const float wgt = (dx ? txB : 1.0f - txB) * (dy ? tyB : 1.0f - tyB);
                        const int idx = (base + (yi * HW + xi) * M_) * 64 + sl * 4;
                        const uint2 u = *reinterpret_cast<const uint2*>(&g_kv[idx]);
                        const float2 kk = __half22float2(*reinterpret_cast<const __half2*>(&u.x));
                        const float2 vv = __half22float2(*reinterpret_cast<const __half2*>(&u.y));
                        bk0 = fmaf(wgt, kk.x, bk0); bk1 = fmaf(wgt, kk.y, bk1);
                        bv0 = fmaf(wgt, vv.x, bv0); bv1 = fmaf(wgt, vv.y, bv1);
                    }
                }
            }

            // scaled logit partials; packed reduction for both points at once.
            // span-16 tree (s=8..1) reduces each half-warp independently.
            float lgA = fmaf(qd.x, ak0, qd.y * ak1) * SCALE;
            float lgB = fmaf(qd.x, bk0, qd.y * bk1) * SCALE;
            __half2 hl = __floats2half2_rn(lgA, lgB);
#pragma unroll
            for (int s = 8; s > 0; s >>= 1) {
                uint32_t u = *reinterpret_cast<uint32_t*>(&hl);
                uint32_t v = __shfl_xor_sync(0xffffffffu, u, s);
                hl = __hadd2(hl, *reinterpret_cast<__half2*>(&v));
            }
            const float2 lf = __half22float2(hl);

            // online no-max softmax accumulation (logits are O(0.1))
            const float eA = __expf(lf.x);
            const float eB = __expf(lf.y);
            ssum += eA + eB;
            o0 = fmaf(eA, av0, o0); o1 = fmaf(eA, av1, o1);
            o0 = fmaf(eB, bv0, o0); o1 = fmaf(eB, bv1, o1);
        }
    }

    const float inv = 1.0f / ssum;
    *reinterpret_cast<__half2*>(&g_att[item * 32 + cl]) =
        __floats2half2_rn(o0 * inv, o1 * inv);
}

// ---------------------------------------------------------------------------
extern "C" void kernel_launch(void* const* d_in, const int* in_sizes, int n_in,
                              void* d_out, int out_size)
{
    const float* query = (const float*)d_in[0];
    const float* ref   = (const float*)d_in[1];
    const float* inp   = (const float*)d_in[2];
    const float* Wv   = (const float*)d_in[5];
    const float* bv   = (const float*)d_in[6];
    const float* Wk   = (const float*)d_in[7];
    const float* bk   = (const float*)d_in[8];
    const float* Wq   = (const float*)d_in[9];
    const float* bq   = (const float*)d_in[10];
    const float* Woff = (const float*)d_in[11];
    const float* boff = (const float*)d_in[12];
    const float* Wout = (const float*)d_in[13];
    const float* bout = (const float*)d_in[14];
    float* out = (float*)d_out;

    void *pkv, *pq, *po, *pa, *pqh, *pinh, *pwh;
    cudaGetSymbolAddress(&pkv,  g_kv);
    cudaGetSymbolAddress(&pq,   g_q);
    cudaGetSymbolAddress(&po,   g_off);
    cudaGetSymbolAddress(&pa,   g_att);
    cudaGetSymbolAddress(&pqh,  g_qh);
    cudaGetSymbolAddress(&pinh, g_inh);
    cudaGetSymbolAddress(&pwh,  g_wh);

    const int rowsV = N_ * LIN_;   // 10880
    const int rowsQ = N_ * LQ_;    // 8000
    const int gyV = rowsV / 128;          // 85
    const int gyQ = (rowsQ + 127) / 128;  // 63

    const int nQ = rowsQ * 256;
    const int nV = rowsV * 256;

    __half* wh = (__half*)pwh;
    CvtAll ca;
    ca.src[0] = inp;   ca.dst[0] = (__half*)pinh; ca.n[0] = nV;
    ca.src[1] = query; ca.dst[1] = (__half*)pqh;  ca.n[1] = nQ;
    const float* wsrc[5] = {Wk, Wv, Wq, Woff, Wout};
    for (int i = 0; i < 5; i++) {
        ca.src[2 + i] = wsrc[i];
        ca.dst[2 + i] = wh + i * 65536;
        ca.n[2 + i] = 65536;
    }
    f2h_all_kernel<<<dim3((nV / 4 + 255) / 256, 7), 256>>>(ca);

    gemm_mma<1><<<dim3(8, gyV), 256>>>((const __half*)pinh, wh + 0 * 65536,
                                       bk, bv, pkv, nullptr, rowsV);
    gemm_mma<0><<<dim3(8, gyQ), 256>>>((const __half*)pqh, wh + 2 * 65536,
                                       bq, boff, pq, po, rowsQ);

    const int nwarps = (N_ * LQ_ * M_) / 2;    // 32000 (2 items per warp)
    sample_attn_kernel<<<nwarps / 8, 256>>>(ref);

    gemm_mma<2><<<dim3(4, gyQ), 256>>>((const __half*)pa, wh + 4 * 65536,
                                       bout, bout, out, nullptr, rowsQ);
}

// round 15
// speedup vs baseline: 1.3956x; 1.0770x over previous
#include <cuda_runtime.h>
#include <cuda_fp16.h>
#include <cstdint>

#define N_ 2
#define LQ_ 4000
#define C_ 256
#define M_ 8
#define L_ 4
#define P_ 4
#define D_ 32
#define LIN_ 5440   // 64*64 + 32*32 + 16*16 + 8*8

// Scratch (static device globals; no allocation allowed)
// g_kv cell layout (64 halves per (pos, m)): group g in 0..7 holds
// {k[4g..4g+3], v[4g..4g+3]} at halves [8g..8g+7].
__device__ __half g_kv [N_ * LIN_ * M_ * 64];
__device__ float  g_q  [N_ * LQ_ * C_];
__device__ float  g_off[N_ * LQ_ * C_];
__device__ __half g_att[N_ * LQ_ * C_];
__device__ __half g_qh [N_ * LQ_ * C_];
__device__ __half g_inh[N_ * LIN_ * C_];
__device__ __half g_wh [5 * C_ * C_];          // Wk, Wv, Wq, Woff, Wout

// ---------------------------------------------------------------------------
// Single fused fp32 -> fp16 converter (7 tensors, grid.y selects)
// ---------------------------------------------------------------------------
struct CvtAll { const float* src[7]; __half* dst[7]; int n[7]; };
__global__ void f2h_all_kernel(CvtAll c) {
    const int which = blockIdx.y;
    const int i = (blockIdx.x * blockDim.x + threadIdx.x) * 4;
    if (i < c.n[which]) {
        float4 v = *reinterpret_cast<const float4*>(c.src[which] + i);
        __half2* p = reinterpret_cast<__half2*>(c.dst[which] + i);
        p[0] = __floats2half2_rn(v.x, v.y);
        p[1] = __floats2half2_rn(v.z, v.w);
    }
}

__device__ __forceinline__ uint32_t smem_u32(const void* p) {
    return static_cast<uint32_t>(__cvta_generic_to_shared(p));
}
__device__ __forceinline__ void cp16(uint32_t dst, const void* src) {
    asm volatile("cp.async.cg.shared.global [%0], [%1], 16;" :: "r"(dst), "l"(src));
}
__device__ __forceinline__ void cp_commit() {
    asm volatile("cp.async.commit_group;");
}
template<int NN>
__device__ __forceinline__ void cp_wait() {
    asm volatile("cp.async.wait_group %0;" :: "n"(NN));
}

// ---------------------------------------------------------------------------
// HMMA GEMM, fp16 inputs, 3-stage cp.async ring (ONE syncthreads per K-iter).
// Columns 0..255 use W, bias b0 -> out slot 0; 256..511 use W+65536, b1 -> 1.
// MODE 0: dual fp32 outs.  MODE 1: kv group-interleave (half).  MODE 2: fp32.
// ---------------------------------------------------------------------------
template<int MODE>
__global__ __launch_bounds__(256) void gemm_mma(
    const __half* __restrict__ A, const __half* __restrict__ W,
    const float* __restrict__ b0, const float* __restrict__ b1,
    void* __restrict__ out0, void* __restrict__ out1, int rows)
{
    __shared__ __half As[3][128 * 40];
    __shared__ __half Bs[3][32 * 64];

    const int tid = threadIdx.x;
    const int lane = tid & 31;
    const int wm = (tid >> 5) & 3;
    const int wn = tid >> 7;
    const int row0 = blockIdx.y * 128;
    const int col0 = blockIdx.x * 64;
    const int wsel = col0 >> 8;
    const int colw = col0 & 255;

    const int ar = tid >> 2;
    const int ac = tid & 3;
    const __half* Ag0 = A + (size_t)min(row0 + ar,      rows - 1) * 256 + ac * 8;
    const __half* Ag1 = A + (size_t)min(row0 + ar + 64, rows - 1) * 256 + ac * 8;
    const uint32_t sA0 = smem_u32(&As[0][ar * 40 + ac * 8]);
    const uint32_t sA1 = smem_u32(&As[0][(ar + 64) * 40 + ac * 8]);
    const int bk = tid >> 3;
    const int bc = tid & 7;
    const __half* Bg = W + wsel * 65536 + (size_t)bk * 256 + colw + bc * 8;
    const uint32_t sB = smem_u32(&Bs[0][bk * 64 + ((bc ^ (bk & 7)) * 8)]);

    const uint32_t stA = 128 * 40 * 2;
    const uint32_t stB = 32 * 64 * 2;

    cp16(sA0, Ag0);
    cp16(sA1, Ag1);
    cp16(sB,  Bg);
    cp_commit();
    cp16(sA0 + stA, Ag0 + 32);
    cp16(sA1 + stA, Ag1 + 32);
    cp16(sB  + stB, Bg + (size_t)32 * 256);
    cp_commit();

    float acc[2][4][4];
#pragma unroll
    for (int mt = 0; mt < 2; mt++)
#pragma unroll
        for (int nt = 0; nt < 4; nt++)
#pragma unroll
            for (int i = 0; i < 4; i++) acc[mt][nt][i] = 0.0f;

    const int ltile = lane >> 3;
    const int ltr   = lane & 7;
    const int a_row_base = wm * 32 + (ltile & 1) * 8 + ltr;
    const int a_ch_off   = ltile >> 1;
    const int b_k_base   = (ltile & 1) * 8 + ltr;
    const int b_ch_off   = ltile >> 1;

#pragma unroll
    for (int it = 0; it < 8; it++) {
        cp_wait<1>();
        __syncthreads();

        const int ps = (it + 2) % 3;
        if (it < 6) {
            const int koff = (it + 2) * 32;
            cp16(sA0 + ps * stA, Ag0 + koff);
            cp16(sA1 + ps * stA, Ag1 + koff);
            cp16(sB  + ps * stB, Bg + (size_t)koff * 256);
        }
        cp_commit();

        const int buf = it % 3;
        const __half* Ab = As[buf];
        const __half* Bb = Bs[buf];
#pragma unroll
        for (int ks = 0; ks < 2; ks++) {
            uint32_t a[2][4], b[2][4];
#pragma unroll
            for (int mt = 0; mt < 2; mt++) {
                const int row = a_row_base + mt * 16;
                const int ch  = ks * 2 + a_ch_off;
                uint32_t addr = smem_u32(&Ab[row * 40 + ch * 8]);
                asm volatile(
                    "ldmatrix.sync.aligned.m8n8.x4.shared.b16 {%0,%1,%2,%3}, [%4];"
                    : "=r"(a[mt][0]), "=r"(a[mt][1]), "=r"(a[mt][2]), "=r"(a[mt][3])
                    : "r"(addr));
            }
#pragma unroll
            for (int p = 0; p < 2; p++) {
                const int k = ks * 16 + b_k_base;
                const int c = wn * 4 + p * 2 + b_ch_off;
                uint32_t addr = smem_u32(&Bb[k * 64 + ((c ^ (k & 7)) * 8)]);
                asm volatile(
                    "ldmatrix.sync.aligned.m8n8.x4.trans.shared.b16 {%0,%1,%2,%3}, [%4];"
                    : "=r"(b[p][0]), "=r"(b[p][1]), "=r"(b[p][2]), "=r"(b[p][3])
                    : "r"(addr));
            }
#pragma unroll
            for (int mt = 0; mt < 2; mt++)
#pragma unroll
                for (int nt = 0; nt < 4; nt++) {
                    const uint32_t bb0 = b[nt >> 1][(nt & 1) * 2 + 0];
                    const uint32_t bb1 = b[nt >> 1][(nt & 1) * 2 + 1];
                    asm volatile(
                        "mma.sync.aligned.m16n8k16.row.col.f32.f16.f16.f32 "
                        "{%0,%1,%2,%3}, {%4,%5,%6,%7}, {%8,%9}, {%0,%1,%2,%3};"
                        : "+f"(acc[mt][nt][0]), "+f"(acc[mt][nt][1]),
                          "+f"(acc[mt][nt][2]), "+f"(acc[mt][nt][3])
                        : "r"(a[mt][0]), "r"(a[mt][1]), "r"(a[mt][2]), "r"(a[mt][3]),
                          "r"(bb0), "r"(bb1));
                }
        }
    }

    const int g  = lane >> 2;
    const int qd = lane & 3;
    const float* bp = wsel ? b1 : b0;
#pragma unroll
    for (int mt = 0; mt < 2; mt++) {
        const int rlo = row0 + wm * 32 + mt * 16 + g;
        const int rhi = rlo + 8;
#pragma unroll
        for (int nt = 0; nt < 4; nt++) {
            const int n = col0 + wn * 32 + nt * 8 + qd * 2;
            const int c = n & 255;
            const float2 bb = *reinterpret_cast<const float2*>(&bp[c]);
            float v0 = acc[mt][nt][0] + bb.x, v1 = acc[mt][nt][1] + bb.y;
            float v2 = acc[mt][nt][2] + bb.x, v3 = acc[mt][nt][3] + bb.y;
            if (MODE == 1) {
                // kv group-interleave: d = c&31 (even). group g = d>>2 holds
                // {k[4g..4g+3], v[4g..4g+3]}; pair (d,d+1) -> offset (d&2),
                // +4 for the value half. Still an adjacent half2 write.
                const int d = c & 31;
                const int oc = ((c >> 5) << 6) + ((d >> 2) << 3) + (d & 2) + (wsel ? 4 : 0);
                __half* o = (__half*)out0;
                if (rlo < rows)
                    *reinterpret_cast<__half2*>(&o[(size_t)rlo * 512 + oc]) = __floats2half2_rn(v0, v1);
                if (rhi < rows)
                    *reinterpret_cast<__half2*>(&o[(size_t)rhi * 512 + oc]) = __floats2half2_rn(v2, v3);
            } else {
                float* o = (MODE == 2) ? (float*)out0 : (wsel ? (float*)out1 : (float*)out0);
                if (rlo < rows)
                    *reinterpret_cast<float2*>(&o[(size_t)rlo * 256 + c]) = make_float2(v0, v1);
                if (rhi < rows)
                    *reinterpret_cast<float2*>(&o[(size_t)rhi * 256 + c]) = make_float2(v2, v3);
            }
        }
    }
}

// ---------------------------------------------------------------------------
// Sampling + key-aware attention. ONE WARP = FOUR (n,q,m) items: 8 lanes per
// item; each sub-lane (sl=lane&7) owns 4 k-channels + 4 v-channels via one
// 16B load per corner. Pairwise point pipeline + packed half2 logit
// reduction (span-8 tree) + online no-max softmax.
// ---------------------------------------------------------------------------
__global__ __launch_bounds__(256) void sample_attn_kernel(
    const float* __restrict__ ref)   // [N, Lq, L, 2]
{
    const int warp = blockIdx.x * 8 + (threadIdx.x >> 5);
    const int lane = threadIdx.x & 31;
    const int item = warp * 4 + (lane >> 3);     // nq*M + m
    if (item >= N_ * LQ_ * M_) return;

    const int m  = item & 7;
    const int nq = item >> 3;
    const int n  = nq / LQ_;
    const int sl = lane & 7;

    const float4 qd = *reinterpret_cast<const float4*>(&g_q[item * 32 + sl * 4]);

    const float* offp = g_off + nq * 256 + m * 32;
    const float* refp = ref + nq * 8;

    const int HWs[4]    = {64, 32, 16, 8};
    const int starts[4] = {0, 4096, 5120, 5376};
    const float SCALE = 0.17677669529663687f;   // 1/sqrt(32)

    float ssum = 0.0f;
    float o0 = 0.0f, o1 = 0.0f, o2 = 0.0f, o3 = 0.0f;

#pragma unroll
    for (int l = 0; l < L_; l++) {
        const float rx = refp[l * 2 + 0];
        const float ry = refp[l * 2 + 1];
        const int HW = HWs[l];
        const float fHW = (float)HW;
        const float fx = rx * fHW - 0.5f;
        const float fy = ry * fHW - 0.5f;
        const int base = (n * LIN_ + starts[l]) * M_ + m;

#pragma unroll
        for (int pp = 0; pp < 2; pp++) {      // pairs of points
            const int pa = l * 4 + pp * 2;

            // both points' offsets in one 16B load (pa even -> aligned)
            const float4 o4 = *reinterpret_cast<const float4*>(&offp[pa * 2]);
            const float xA = fx + o4.x, yA = fy + o4.y;
            const float xB = fx + o4.z, yB = fy + o4.w;
            const float xA0f = floorf(xA), yA0f = floorf(yA);
            const float xB0f = floorf(xB), yB0f = floorf(yB);
            const float txA = xA - xA0f, tyA = yA - yA0f;
            const float txB = xB - xB0f, tyB = yB - yB0f;
            const int xA0 = (int)xA0f, yA0 = (int)yA0f;
            const int xB0 = (int)xB0f, yB0 = (int)yB0f;

            // per-lane accumulators: 4 k + 4 v channels, points A and B
            float ak0 = 0.f, ak1 = 0.f, ak2 = 0.f, ak3 = 0.f;
            float av0 = 0.f, av1 = 0.f, av2 = 0.f, av3 = 0.f;
            float bk0 = 0.f, bk1 = 0.f, bk2 = 0.f, bk3 = 0.f;
            float bv0 = 0.f, bv1 = 0.f, bv2 = 0.f, bv3 = 0.f;
#pragma unroll
            for (int c = 0; c < 4; c++) {
                const int dx = c & 1;
                const int dy = c >> 1;
                // point A corner
                {
                    const int xi = xA0 + dx, yi = yA0 + dy;
                    if (xi >= 0 && xi < HW && yi >= 0 && yi < HW) {
                        const float wgt = (dx ? txA : 1.0f - txA) * (dy ? tyA : 1.0f - tyA);
                        const int idx = (base + (yi * HW + xi) * M_) * 64 + sl * 8;
                        const uint4 u = *reinterpret_cast<const uint4*>(&g_kv[idx]);
                        const float2 k01 = __half22float2(*reinterpret_cast<const __half2*>(&u.x));
                        const float2 k23 = __half22float2(*reinterpret_cast<const __half2*>(&u.y));
                        const float2 v01 = __half22float2(*reinterpret_cast<const __half2*>(&u.z));
                        const float2 v23 = __half22float2(*reinterpret_cast<const __half2*>(&u.w));
                        ak0 = fmaf(wgt, k01.x, ak0); ak1 = fmaf(wgt, k01.y, ak1);
                        ak2 = fmaf(wgt, k23.x, ak2); ak3 = fmaf(wgt, k23.y, ak3);
                        av0 = fmaf(wgt, v01.x, av0); av1 = fmaf(wgt, v01.y, av1);
                        av2 = fmaf(wgt, v23.x, av2); av3 = fmaf(wgt, v23.y, av3);
                    }
                }
                // point B corner
                {
                    const int xi = xB0 + dx, yi = yB0 + dy;
                    if (xi >= 0 && xi < HW && yi >= 0 && yi < HW) {
                        const float wgt = (dx ? txB : 1.0f - txB) * (dy ? tyB : 1.0f - tyB);
                        const int idx = (base + (yi * HW + xi) * M_) * 64 + sl * 8;
                        const uint4 u = *reinterpret_cast<const uint4*>(&g_kv[idx]);
                        const float2 k01 = __half22float2(*reinterpret_cast<const __half2*>(&u.x));
                        const float2 k23 = __half22float2(*reinterpret_cast<const __half2*>(&u.y));
                        const float2 v01 = __half22float2(*reinterpret_cast<const __half2*>(&u.z));
                        const float2 v23 = __half22float2(*reinterpret_cast<const __half2*>(&u.w));
                        bk0 = fmaf(wgt, k01.x, bk0); bk1 = fmaf(wgt, k01.y, bk1);
                        bk2 = fmaf(wgt, k23.x, bk2); bk3 = fmaf(wgt, k23.y, bk3);
                        bv0 = fmaf(wgt, v01.x, bv0); bv1 = fmaf(wgt, v01.y, bv1);
                        bv2 = fmaf(wgt, v23.x, bv2); bv3 = fmaf(wgt, v23.y, bv3);
                    }
                }
            }

            // scaled logit partials; packed reduction for both points at once.
            // span-8 tree (s=4,2,1) reduces each 8-lane item independently.
            float lgA = (fmaf(qd.x, ak0, qd.y * ak1) + fmaf(qd.z, ak2, qd.w * ak3)) * SCALE;
            float lgB = (fmaf(qd.x, bk0, qd.y * bk1) + fmaf(qd.z, bk2, qd.w * bk3)) * SCALE;
            __half2 hl = __floats2half2_rn(lgA, lgB);
#pragma unroll
            for (int s = 4; s > 0; s >>= 1) {
                uint32_t u = *reinterpret_cast<uint32_t*>(&hl);
                uint32_t v = __shfl_xor_sync(0xffffffffu, u, s);
                hl = __hadd2(hl, *reinterpret_cast<__half2*>(&v));
            }
            const float2 lf = __half22float2(hl);

            // online no-max softmax accumulation (logits are O(0.1))
            const float eA = __expf(lf.x);
            const float eB = __expf(lf.y);
            ssum += eA + eB;
            o0 = fmaf(eA, av0, o0); o1 = fmaf(eA, av1, o1);
            o2 = fmaf(eA, av2, o2); o3 = fmaf(eA, av3, o3);
            o0 = fmaf(eB, bv0, o0); o1 = fmaf(eB, bv1, o1);
            o2 = fmaf(eB, bv2, o2); o3 = fmaf(eB, bv3, o3);
        }
    }

    const float inv = 1.0f / ssum;
    __half2 w0 = __floats2half2_rn(o0 * inv, o1 * inv);
    __half2 w1 = __floats2half2_rn(o2 * inv, o3 * inv);
    uint2 pkd;
    pkd.x = *reinterpret_cast<uint32_t*>(&w0);
    pkd.y = *reinterpret_cast<uint32_t*>(&w1);
    *reinterpret_cast<uint2*>(&g_att[item * 32 + sl * 4]) = pkd;
}

// ---------------------------------------------------------------------------
extern "C" void kernel_launch(void* const* d_in, const int* in_sizes, int n_in,
                              void* d_out, int out_size)
{
    const float* query = (const float*)d_in[0];
    const float* ref   = (const float*)d_in[1];
    const float* inp   = (const float*)d_in[2];
    const float* Wv   = (const float*)d_in[5];
    const float* bv   = (const float*)d_in[6];
    const float* Wk   = (const float*)d_in[7];
    const float* bk   = (const float*)d_in[8];
    const float* Wq   = (const float*)d_in[9];
    const float* bq   = (const float*)d_in[10];
    const float* Woff = (const float*)d_in[11];
    const float* boff = (const float*)d_in[12];
    const float* Wout = (const float*)d_in[13];
    const float* bout = (const float*)d_in[14];
    float* out = (float*)d_out;

    void *pkv, *pq, *po, *pa, *pqh, *pinh, *pwh;
    cudaGetSymbolAddress(&pkv,  g_kv);
    cudaGetSymbolAddress(&pq,   g_q);
    cudaGetSymbolAddress(&po,   g_off);
    cudaGetSymbolAddress(&pa,   g_att);
    cudaGetSymbolAddress(&pqh,  g_qh);
    cudaGetSymbolAddress(&pinh, g_inh);
    cudaGetSymbolAddress(&pwh,  g_wh);

    const int rowsV = N_ * LIN_;   // 10880
    const int rowsQ = N_ * LQ_;    // 8000
    const int gyV = rowsV / 128;          // 85
    const int gyQ = (rowsQ + 127) / 128;  // 63

    const int nQ = rowsQ * 256;
    const int nV = rowsV * 256;

    __half* wh = (__half*)pwh;
    CvtAll ca;
    ca.src[0] = inp;   ca.dst[0] = (__half*)pinh; ca.n[0] = nV;
    ca.src[1] = query; ca.dst[1] = (__half*)pqh;  ca.n[1] = nQ;
    const float* wsrc[5] = {Wk, Wv, Wq, Woff, Wout};
    for (int i = 0; i < 5; i++) {
        ca.src[2 + i] = wsrc[i];
        ca.dst[2 + i] = wh + i * 65536;
        ca.n[2 + i] = 65536;
    }
    f2h_all_kernel<<<dim3((nV / 4 + 255) / 256, 7), 256>>>(ca);

    gemm_mma<1><<<dim3(8, gyV), 256>>>((const __half*)pinh, wh + 0 * 65536,
                                       bk, bv, pkv, nullptr, rowsV);
    gemm_mma<0><<<dim3(8, gyQ), 256>>>((const __half*)pqh, wh + 2 * 65536,
                                       bq, boff, pq, po, rowsQ);

    const int nwarps = (N_ * LQ_ * M_) / 4;    // 16000 (4 items per warp)
    sample_attn_kernel<<<nwarps / 8, 256>>>(ref);

    gemm_mma<2><<<dim3(4, gyQ), 256>>>((const __half*)pa, wh + 4 * 65536,
                                       bout, bout, out, nullptr, rowsQ);
}

// round 16
// speedup vs baseline: 1.4272x; 1.0227x over previous
#include <cuda_runtime.h>
#include <cuda_fp16.h>
#include <cstdint>

#define N_ 2
#define LQ_ 4000
#define C_ 256
#define M_ 8
#define L_ 4
#define P_ 4
#define D_ 32
#define LIN_ 5440   // 64*64 + 32*32 + 16*16 + 8*8

// Scratch (static device globals; no allocation allowed)
// g_kv cell layout (64 halves per (pos, m)): group g in 0..7 holds
// {k[4g..4g+3], v[4g..4g+3]} at halves [8g..8g+7].
__device__ __half g_kv [N_ * LIN_ * M_ * 64];
__device__ float  g_q  [N_ * LQ_ * C_];
__device__ float  g_off[N_ * LQ_ * C_];
__device__ __half g_att[N_ * LQ_ * C_];
__device__ __half g_qh [N_ * LQ_ * C_];
__device__ __half g_inh[N_ * LIN_ * C_];
__device__ __half g_wh [5 * C_ * C_];          // Wk, Wv, Wq, Woff, Wout

// ---------------------------------------------------------------------------
// Single fused fp32 -> fp16 converter (7 tensors, grid.y selects)
// ---------------------------------------------------------------------------
struct CvtAll { const float* src[7]; __half* dst[7]; int n[7]; };
__global__ void f2h_all_kernel(CvtAll c) {
    const int which = blockIdx.y;
    const int i = (blockIdx.x * blockDim.x + threadIdx.x) * 4;
    if (i < c.n[which]) {
        float4 v = *reinterpret_cast<const float4*>(c.src[which] + i);
        __half2* p = reinterpret_cast<__half2*>(c.dst[which] + i);
        p[0] = __floats2half2_rn(v.x, v.y);
        p[1] = __floats2half2_rn(v.z, v.w);
    }
}

__device__ __forceinline__ uint32_t smem_u32(const void* p) {
    return static_cast<uint32_t>(__cvta_generic_to_shared(p));
}
__device__ __forceinline__ void cp16(uint32_t dst, const void* src) {
    asm volatile("cp.async.cg.shared.global [%0], [%1], 16;" :: "r"(dst), "l"(src));
}
__device__ __forceinline__ void cp_commit() {
    asm volatile("cp.async.commit_group;");
}
template<int NN>
__device__ __forceinline__ void cp_wait() {
    asm volatile("cp.async.wait_group %0;" :: "n"(NN));
}

// ---------------------------------------------------------------------------
// HMMA GEMM, fp16 inputs, 3-stage cp.async ring (ONE syncthreads per K-iter).
// Columns 0..255 use W, bias b0 -> out slot 0; 256..511 use W+65536, b1 -> 1.
// MODE 0: dual fp32 outs.  MODE 1: kv group-interleave (half).  MODE 2: fp32.
// ---------------------------------------------------------------------------
template<int MODE>
__global__ __launch_bounds__(256) void gemm_mma(
    const __half* __restrict__ A, const __half* __restrict__ W,
    const float* __restrict__ b0, const float* __restrict__ b1,
    void* __restrict__ out0, void* __restrict__ out1, int rows)
{
    __shared__ __half As[3][128 * 40];
    __shared__ __half Bs[3][32 * 64];

    const int tid = threadIdx.x;
    const int lane = tid & 31;
    const int wm = (tid >> 5) & 3;
    const int wn = tid >> 7;
    const int row0 = blockIdx.y * 128;
    const int col0 = blockIdx.x * 64;
    const int wsel = col0 >> 8;
    const int colw = col0 & 255;

    const int ar = tid >> 2;
    const int ac = tid & 3;
    const __half* Ag0 = A + (size_t)min(row0 + ar,      rows - 1) * 256 + ac * 8;
    const __half* Ag1 = A + (size_t)min(row0 + ar + 64, rows - 1) * 256 + ac * 8;
    const uint32_t sA0 = smem_u32(&As[0][ar * 40 + ac * 8]);
    const uint32_t sA1 = smem_u32(&As[0][(ar + 64) * 40 + ac * 8]);
    const int bk = tid >> 3;
    const int bc = tid & 7;
    const __half* Bg = W + wsel * 65536 + (size_t)bk * 256 + colw + bc * 8;
    const uint32_t sB = smem_u32(&Bs[0][bk * 64 + ((bc ^ (bk & 7)) * 8)]);

    const uint32_t stA = 128 * 40 * 2;
    const uint32_t stB = 32 * 64 * 2;

    cp16(sA0, Ag0);
    cp16(sA1, Ag1);
    cp16(sB,  Bg);
    cp_commit();
    cp16(sA0 + stA, Ag0 + 32);
    cp16(sA1 + stA, Ag1 + 32);
    cp16(sB  + stB, Bg + (size_t)32 * 256);
    cp_commit();

    float acc[2][4][4];
#pragma unroll
    for (int mt = 0; mt < 2; mt++)
#pragma unroll
        for (int nt = 0; nt < 4; nt++)
#pragma unroll
            for (int i = 0; i < 4; i++) acc[mt][nt][i] = 0.0f;

    const int ltile = lane >> 3;
    const int ltr   = lane & 7;
    const int a_row_base = wm * 32 + (ltile & 1) * 8 + ltr;
    const int a_ch_off   = ltile >> 1;
    const int b_k_base   = (ltile & 1) * 8 + ltr;
    const int b_ch_off   = ltile >> 1;

#pragma unroll
    for (int it = 0; it < 8; it++) {
        cp_wait<1>();
        __syncthreads();

        const int ps = (it + 2) % 3;
        if (it < 6) {
            const int koff = (it + 2) * 32;
            cp16(sA0 + ps * stA, Ag0 + koff);
            cp16(sA1 + ps * stA, Ag1 + koff);
            cp16(sB  + ps * stB, Bg + (size_t)koff * 256);
        }
        cp_commit();

        const int buf = it % 3;
        const __half* Ab = As[buf];
        const __half* Bb = Bs[buf];
#pragma unroll
        for (int ks = 0; ks < 2; ks++) {
            uint32_t a[2][4], b[2][4];
#pragma unroll
            for (int mt = 0; mt < 2; mt++) {
                const int row = a_row_base + mt * 16;
                const int ch  = ks * 2 + a_ch_off;
                uint32_t addr = smem_u32(&Ab[row * 40 + ch * 8]);
                asm volatile(
                    "ldmatrix.sync.aligned.m8n8.x4.shared.b16 {%0,%1,%2,%3}, [%4];"
                    : "=r"(a[mt][0]), "=r"(a[mt][1]), "=r"(a[mt][2]), "=r"(a[mt][3])
                    : "r"(addr));
            }
#pragma unroll
            for (int p = 0; p < 2; p++) {
                const int k = ks * 16 + b_k_base;
                const int c = wn * 4 + p * 2 + b_ch_off;
                uint32_t addr = smem_u32(&Bb[k * 64 + ((c ^ (k & 7)) * 8)]);
                asm volatile(
                    "ldmatrix.sync.aligned.m8n8.x4.trans.shared.b16 {%0,%1,%2,%3}, [%4];"
                    : "=r"(b[p][0]), "=r"(b[p][1]), "=r"(b[p][2]), "=r"(b[p][3])
                    : "r"(addr));
            }
#pragma unroll
            for (int mt = 0; mt < 2; mt++)
#pragma unroll
                for (int nt = 0; nt < 4; nt++) {
                    const uint32_t bb0 = b[nt >> 1][(nt & 1) * 2 + 0];
                    const uint32_t bb1 = b[nt >> 1][(nt & 1) * 2 + 1];
                    asm volatile(
                        "mma.sync.aligned.m16n8k16.row.col.f32.f16.f16.f32 "
                        "{%0,%1,%2,%3}, {%4,%5,%6,%7}, {%8,%9}, {%0,%1,%2,%3};"
                        : "+f"(acc[mt][nt][0]), "+f"(acc[mt][nt][1]),
                          "+f"(acc[mt][nt][2]), "+f"(acc[mt][nt][3])
                        : "r"(a[mt][0]), "r"(a[mt][1]), "r"(a[mt][2]), "r"(a[mt][3]),
                          "r"(bb0), "r"(bb1));
                }
        }
    }

    const int g  = lane >> 2;
    const int qd = lane & 3;
    const float* bp = wsel ? b1 : b0;
#pragma unroll
    for (int mt = 0; mt < 2; mt++) {
        const int rlo = row0 + wm * 32 + mt * 16 + g;
        const int rhi = rlo + 8;
#pragma unroll
        for (int nt = 0; nt < 4; nt++) {
            const int n = col0 + wn * 32 + nt * 8 + qd * 2;
            const int c = n & 255;
            const float2 bb = *reinterpret_cast<const float2*>(&bp[c]);
            float v0 = acc[mt][nt][0] + bb.x, v1 = acc[mt][nt][1] + bb.y;
            float v2 = acc[mt][nt][2] + bb.x, v3 = acc[mt][nt][3] + bb.y;
            if (MODE == 1) {
                // kv group-interleave: d = c&31 (even). group g = d>>2 holds
                // {k[4g..4g+3], v[4g..4g+3]}; pair (d,d+1) -> offset (d&2),
                // +4 for the value half. Still an adjacent half2 write.
                const int d = c & 31;
                const int oc = ((c >> 5) << 6) + ((d >> 2) << 3) + (d & 2) + (wsel ? 4 : 0);
                __half* o = (__half*)out0;
                if (rlo < rows)
                    *reinterpret_cast<__half2*>(&o[(size_t)rlo * 512 + oc]) = __floats2half2_rn(v0, v1);
                if (rhi < rows)
                    *reinterpret_cast<__half2*>(&o[(size_t)rhi * 512 + oc]) = __floats2half2_rn(v2, v3);
            } else {
                float* o = (MODE == 2) ? (float*)out0 : (wsel ? (float*)out1 : (float*)out0);
                if (rlo < rows)
                    *reinterpret_cast<float2*>(&o[(size_t)rlo * 256 + c]) = make_float2(v0, v1);
                if (rhi < rows)
                    *reinterpret_cast<float2*>(&o[(size_t)rhi * 256 + c]) = make_float2(v2, v3);
            }
        }
    }
}

// ---------------------------------------------------------------------------
// Sampling + key-aware attention. ONE WARP = FOUR (n,q,m) items: 8 lanes per
// item; each sub-lane (sl=lane&7) owns 4 k-channels + 4 v-channels via one
// 16B load per corner. Key-dot FOLDED into the corner loop (no k
// accumulators -> fewer regs), qd pre-scaled by 1/sqrt(D). Pairwise point
// pipeline + packed half2 span-8 reduction + online no-max softmax.
// __launch_bounds__(256, 4): pin regs at 64 for 4 CTAs/SM.
// ---------------------------------------------------------------------------
__global__ __launch_bounds__(256, 4) void sample_attn_kernel(
    const float* __restrict__ ref)   // [N, Lq, L, 2]
{
    const int warp = blockIdx.x * 8 + (threadIdx.x >> 5);
    const int lane = threadIdx.x & 31;
    const int item = warp * 4 + (lane >> 3);     // nq*M + m
    if (item >= N_ * LQ_ * M_) return;

    const int m  = item & 7;
    const int nq = item >> 3;
    const int n  = nq / LQ_;
    const int sl = lane & 7;

    const float SCALE = 0.17677669529663687f;   // 1/sqrt(32)
    float4 qd = *reinterpret_cast<const float4*>(&g_q[item * 32 + sl * 4]);
    qd.x *= SCALE; qd.y *= SCALE; qd.z *= SCALE; qd.w *= SCALE;

    const float* offp = g_off + nq * 256 + m * 32;
    const float* refp = ref + nq * 8;

    const int HWs[4]    = {64, 32, 16, 8};
    const int starts[4] = {0, 4096, 5120, 5376};

    float ssum = 0.0f;
    float o0 = 0.0f, o1 = 0.0f, o2 = 0.0f, o3 = 0.0f;

#pragma unroll
    for (int l = 0; l < L_; l++) {
        const float rx = refp[l * 2 + 0];
        const float ry = refp[l * 2 + 1];
        const int HW = HWs[l];
        const float fHW = (float)HW;
        const float fx = rx * fHW - 0.5f;
        const float fy = ry * fHW - 0.5f;
        const int base = (n * LIN_ + starts[l]) * M_ + m;

#pragma unroll
        for (int pp = 0; pp < 2; pp++) {      // pairs of points
            const int pa = l * 4 + pp * 2;

            // both points' offsets in one 16B load (pa even -> aligned)
            const float4 o4 = *reinterpret_cast<const float4*>(&offp[pa * 2]);
            const float xA = fx + o4.x, yA = fy + o4.y;
            const float xB = fx + o4.z, yB = fy + o4.w;
            const float xA0f = floorf(xA), yA0f = floorf(yA);
            const float xB0f = floorf(xB), yB0f = floorf(yB);
            const float txA = xA - xA0f, tyA = yA - yA0f;
            const float txB = xB - xB0f, tyB = yB - yB0f;
            const int xA0 = (int)xA0f, yA0 = (int)yA0f;
            const int xB0 = (int)xB0f, yB0 = (int)yB0f;

            // per-lane accumulators: folded k-dot + 4 v channels, points A,B
            float lgA = 0.f, lgB = 0.f;
            float av0 = 0.f, av1 = 0.f, av2 = 0.f, av3 = 0.f;
            float bv0 = 0.f, bv1 = 0.f, bv2 = 0.f, bv3 = 0.f;
#pragma unroll
            for (int c = 0; c < 4; c++) {
                const int dx = c & 1;
                const int dy = c >> 1;
                // point A corner
                {
                    const int xi = xA0 + dx, yi = yA0 + dy;
                    if (xi >= 0 && xi < HW && yi >= 0 && yi < HW) {
                        const float wgt = (dx ? txA : 1.0f - txA) * (dy ? tyA : 1.0f - tyA);
                        const int idx = (base + (yi * HW + xi) * M_) * 64 + sl * 8;
                        const uint4 u = *reinterpret_cast<const uint4*>(&g_kv[idx]);
                        const float2 k01 = __half22float2(*reinterpret_cast<const __half2*>(&u.x));
                        const float2 k23 = __half22float2(*reinterpret_cast<const __half2*>(&u.y));
                        const float2 v01 = __half22float2(*reinterpret_cast<const __half2*>(&u.z));
                        const float2 v23 = __half22float2(*reinterpret_cast<const __half2*>(&u.w));
                        float dot = qd.x * k01.x;
                        dot = fmaf(qd.y, k01.y, dot);
                        dot = fmaf(qd.z, k23.x, dot);
                        dot = fmaf(qd.w, k23.y, dot);
                        lgA = fmaf(wgt, dot, lgA);
                        av0 = fmaf(wgt, v01.x, av0); av1 = fmaf(wgt, v01.y, av1);
                        av2 = fmaf(wgt, v23.x, av2); av3 = fmaf(wgt, v23.y, av3);
                    }
                }
                // point B corner
                {
                    const int xi = xB0 + dx, yi = yB0 + dy;
                    if (xi >= 0 && xi < HW && yi >= 0 && yi < HW) {
                        const float wgt = (dx ? txB : 1.0f - txB) * (dy ? tyB : 1.0f - tyB);
                        const int idx = (base + (yi * HW + xi) * M_) * 64 + sl * 8;
                        const uint4 u = *reinterpret_cast<const uint4*>(&g_kv[idx]);
                        const float2 k01 = __half22float2(*reinterpret_cast<const __half2*>(&u.x));
                        const float2 k23 = __half22float2(*reinterpret_cast<const __half2*>(&u.y));
                        const float2 v01 = __half22float2(*reinterpret_cast<const __half2*>(&u.z));
                        const float2 v23 = __half22float2(*reinterpret_cast<const __half2*>(&u.w));
                        float dot = qd.x * k01.x;
                        dot = fmaf(qd.y, k01.y, dot);
                        dot = fmaf(qd.z, k23.x, dot);
                        dot = fmaf(qd.w, k23.y, dot);
                        lgB = fmaf(wgt, dot, lgB);
                        bv0 = fmaf(wgt, v01.x, bv0); bv1 = fmaf(wgt, v01.y, bv1);
                        bv2 = fmaf(wgt, v23.x, bv2); bv3 = fmaf(wgt, v23.y, bv3);
                    }
                }
            }

            // packed reduction for both points at once; span-8 tree (s=4,2,1)
            __half2 hl = __floats2half2_rn(lgA, lgB);
#pragma unroll
            for (int s = 4; s > 0; s >>= 1) {
                uint32_t u = *reinterpret_cast<uint32_t*>(&hl);
                uint32_t v = __shfl_xor_sync(0xffffffffu, u, s);
                hl = __hadd2(hl, *reinterpret_cast<__half2*>(&v));
            }
            const float2 lf = __half22float2(hl);

            // online no-max softmax accumulation (logits are O(0.1))
            const float eA = __expf(lf.x);
            const float eB = __expf(lf.y);
            ssum += eA + eB;
            o0 = fmaf(eA, av0, o0); o1 = fmaf(eA, av1, o1);
            o2 = fmaf(eA, av2, o2); o3 = fmaf(eA, av3, o3);
            o0 = fmaf(eB, bv0, o0); o1 = fmaf(eB, bv1, o1);
            o2 = fmaf(eB, bv2, o2); o3 = fmaf(eB, bv3, o3);
        }
    }

    const float inv = 1.0f / ssum;
    __half2 w0 = __floats2half2_rn(o0 * inv, o1 * inv);
    __half2 w1 = __floats2half2_rn(o2 * inv, o3 * inv);
    uint2 pkd;
    pkd.x = *reinterpret_cast<uint32_t*>(&w0);
    pkd.y = *reinterpret_cast<uint32_t*>(&w1);
    *reinterpret_cast<uint2*>(&g_att[item * 32 + sl * 4]) = pkd;
}

// ---------------------------------------------------------------------------
extern "C" void kernel_launch(void* const* d_in, const int* in_sizes, int n_in,
                              void* d_out, int out_size)
{
    const float* query = (const float*)d_in[0];
    const float* ref   = (const float*)d_in[1];
    const float* inp   = (const float*)d_in[2];
    const float* Wv   = (const float*)d_in[5];
    const float* bv   = (const float*)d_in[6];
    const float* Wk   = (const float*)d_in[7];
    const float* bk   = (const float*)d_in[8];
    const float* Wq   = (const float*)d_in[9];
    const float* bq   = (const float*)d_in[10];
    const float* Woff = (const float*)d_in[11];
    const float* boff = (const float*)d_in[12];
    const float* Wout = (const float*)d_in[13];
    const float* bout = (const float*)d_in[14];
    float* out = (float*)d_out;

    void *pkv, *pq, *po, *pa, *pqh, *pinh, *pwh;
    cudaGetSymbolAddress(&pkv,  g_kv);
    cudaGetSymbolAddress(&pq,   g_q);
    cudaGetSymbolAddress(&po,   g_off);
    cudaGetSymbolAddress(&pa,   g_att);
    cudaGetSymbolAddress(&pqh,  g_qh);
    cudaGetSymbolAddress(&pinh, g_inh);
    cudaGetSymbolAddress(&pwh,  g_wh);

    const int rowsV = N_ * LIN_;   // 10880
    const int rowsQ = N_ * LQ_;    // 8000
    const int gyV = rowsV / 128;          // 85
    const int gyQ = (rowsQ + 127) / 128;  // 63

    const int nQ = rowsQ * 256;
    const int nV = rowsV * 256;

    __half* wh = (__half*)pwh;
    CvtAll ca;
    ca.src[0] = inp;   ca.dst[0] = (__half*)pinh; ca.n[0] = nV;
    ca.src[1] = query; ca.dst[1] = (__half*)pqh;  ca.n[1] = nQ;
    const float* wsrc[5] = {Wk, Wv, Wq, Woff, Wout};
    for (int i = 0; i < 5; i++) {
        ca.src[2 + i] = wsrc[i];
        ca.dst[2 + i] = wh + i * 65536;
        ca.n[2 + i] = 65536;
    }
    f2h_all_kernel<<<dim3((nV / 4 + 255) / 256, 7), 256>>>(ca);

    gemm_mma<1><<<dim3(8, gyV), 256>>>((const __half*)pinh, wh + 0 * 65536,
                                       bk, bv, pkv, nullptr, rowsV);
    gemm_mma<0><<<dim3(8, gyQ), 256>>>((const __half*)pqh, wh + 2 * 65536,
                                       bq, boff, pq, po, rowsQ);

    const int nwarps = (N_ * LQ_ * M_) / 4;    // 16000 (4 items per warp)
    sample_attn_kernel<<<nwarps / 8, 256>>>(ref);

    gemm_mma<2><<<dim3(4, gyQ), 256>>>((const __half*)pa, wh + 4 * 65536,
                                       bout, bout, out, nullptr, rowsQ);
}